// round 14
// baseline (speedup 1.0000x reference)
#include <cuda_runtime.h>

#define BATCH 4
#define NCH   64
#define NPTS  20000
#define XSZ   512
#define YSZ   512
#define YTILE 128
#define NYT   (YSZ / YTILE)   // 4

// feature-map pixel counts
#define P3 (48 * 160)   // 7680
#define P4 (24 * 80)    // 1920
#define P5 (12 * 40)    // 480

// -------- device scratch (zero-initialized; zero == empty marker) --------
__device__ int   g_idx[BATCH * XSZ * YSZ];      // winner (point index + 1) per pixel, 0 = empty
__device__ float g_t3[BATCH * P3 * NCH];        // features transposed to [b][pix][c]
__device__ float g_t4[BATCH * P4 * NCH];
__device__ float g_t5[BATCH * P5 * NCH];

// -------- combined prologue: transpose blocks + scatter blocks in one launch --------
#define T3_BLKS (BATCH * 2 * (P3 / 32))   // 1920
#define T4_BLKS (BATCH * 2 * (P4 / 32))   // 480
#define T5_BLKS (BATCH * 2 * (P5 / 32))   // 120
#define T_BLKS  (T3_BLKS + T4_BLKS + T5_BLKS)
#define SC_BLKS ((BATCH * NPTS + 255) / 256)   // 313
#define PRE_BLKS (T_BLKS + SC_BLKS)

__global__ void k_pre(const float* __restrict__ c3,
                      const float* __restrict__ c4,
                      const float* __restrict__ c5,
                      const int*   __restrict__ coors,
                      const int*   __restrict__ contain) {
    __shared__ float s[32][33];
    int bid = blockIdx.x;

    if (bid >= T_BLKS) {
        // ---- scatter: last-update-wins == highest (p+1) wins; 0 = empty ----
        int i = (bid - T_BLKS) * 256 + threadIdx.y * 32 + threadIdx.x;
        if (i >= BATCH * NPTS) return;
        if (contain[i] <= 0) return;
        int b  = i / NPTS;
        int p  = i - b * NPTS;
        int cx = coors[i * 3 + 1];
        int cy = coors[i * 3 + 2];
        if ((unsigned)cx >= XSZ || (unsigned)cy >= YSZ) return;
        atomicMax(&g_idx[(b * XSZ + cx) * YSZ + cy], p + 1);
        return;
    }

    // ---- tiled transpose: [C=64][P] -> [P][C=64] per (map, b) ----
    const float* src;
    float* dst;
    int P;
    if (bid < T3_BLKS)                { src = c3; dst = g_t3; P = P3; }
    else if (bid < T3_BLKS + T4_BLKS) { bid -= T3_BLKS; src = c4; dst = g_t4; P = P4; }
    else                              { bid -= T3_BLKS + T4_BLKS; src = c5; dst = g_t5; P = P5; }

    int ptiles = P >> 5;
    int b   = bid / (2 * ptiles);
    int rem = bid - b * (2 * ptiles);
    int c0  = (rem / ptiles) << 5;
    int p0  = (rem % ptiles) << 5;
    src += (size_t)b * NCH * P;
    dst += (size_t)b * P * NCH;

    int tx = threadIdx.x, ty = threadIdx.y;
    #pragma unroll
    for (int j = 0; j < 4; j++)
        s[ty + j * 8][tx] = src[(c0 + ty + j * 8) * P + p0 + tx];
    __syncthreads();
    #pragma unroll
    for (int j = 0; j < 4; j++)
        dst[(size_t)(p0 + ty + j * 8) * NCH + c0 + tx] = s[tx][ty + j * 8];
}

// -------- bilinear sample of one transposed map, warp-wide over channels --------
template<int H, int W>
__device__ __forceinline__ void sample_map(const float* __restrict__ t,   // [pix][C] for this batch
                                           float px, float py, int lane,
                                           float d, float2& acc) {
    float x = px * (float)(W - 1);
    float y = py * (float)(H - 1);
    float x0f = floorf(x), y0f = floorf(y);
    float wx = x - x0f,    wy = y - y0f;
    int x0 = (int)x0f, y0 = (int)y0f;
    int x1 = x0 + 1,   y1 = y0 + 1;

    float v00 = (x0 >= 0 && x0 < W && y0 >= 0 && y0 < H) ? 1.f : 0.f;
    float v10 = (x1 >= 0 && x1 < W && y0 >= 0 && y0 < H) ? 1.f : 0.f;
    float v01 = (x0 >= 0 && x0 < W && y1 >= 0 && y1 < H) ? 1.f : 0.f;
    float v11 = (x1 >= 0 && x1 < W && y1 >= 0 && y1 < H) ? 1.f : 0.f;

    int cx0 = min(max(x0, 0), W - 1);
    int cx1 = min(max(x1, 0), W - 1);
    int cy0 = min(max(y0, 0), H - 1);
    int cy1 = min(max(y1, 0), H - 1);

    float w00 = (1.f - wx) * (1.f - wy) * v00;
    float w10 =        wx  * (1.f - wy) * v10;
    float w01 = (1.f - wx) *        wy  * v01;
    float w11 =        wx  *        wy  * v11;

    const float2* p00 = (const float2*)(t + (cy0 * W + cx0) * NCH) + lane;
    const float2* p10 = (const float2*)(t + (cy0 * W + cx1) * NCH) + lane;
    const float2* p01 = (const float2*)(t + (cy1 * W + cx0) * NCH) + lane;
    const float2* p11 = (const float2*)(t + (cy1 * W + cx1) * NCH) + lane;
    float2 a00 = *p00, a10 = *p10, a01 = *p01, a11 = *p11;

    acc.x += d * (w00 * a00.x + w10 * a10.x + w01 * a01.x + w11 * a11.x);
    acc.y += d * (w00 * a00.y + w10 * a10.y + w01 * a01.y + w11 * a11.y);
}

// -------- one full 3-map sample + blend + swizzled smem store --------
__device__ __forceinline__ void do_point(int e, int b, int x, int y0, int lane,
                                         const float* __restrict__ pnts,
                                         const float* __restrict__ dyn,
                                         float* __restrict__ sm) {
    int yloc = e >> 15;
    int p    = e & 0x7FFF;
    int cy   = y0 + yloc;

    float2 pxy = ((const float2*)pnts)[b * NPTS + p];
    float d0 = dyn[((b * 3 + 0) * XSZ + x) * YSZ + cy];
    float d1 = dyn[((b * 3 + 1) * XSZ + x) * YSZ + cy];
    float d2 = dyn[((b * 3 + 2) * XSZ + x) * YSZ + cy];

    float2 acc = make_float2(0.f, 0.f);
    sample_map<48, 160>(g_t3 + b * P3 * NCH, pxy.x, pxy.y, lane, d0, acc);
    sample_map<24,  80>(g_t4 + b * P4 * NCH, pxy.x, pxy.y, lane, d1, acc);
    sample_map<12,  40>(g_t5 + b * P5 * NCH, pxy.x, pxy.y, lane, d2, acc);

    int g = (yloc >> 2) & 31;
    sm[yloc * NCH + ((2 * lane)     ^ g)] = acc.x;
    sm[yloc * NCH + ((2 * lane + 1) ^ g)] = acc.y;
}

// -------- fused: zero-fill + sample + blend, streaming the output once --------
// One block per (b, x, ytile=128). 256 threads = 8 warps.
// SINGLE CHANGE vs 63.5us kernel: each warp samples TWO points per loop
// iteration (independent chains -> 2x memory-level parallelism in the
// latency-bound sampling phase).
__global__ __launch_bounds__(256) void k_fused(const float* __restrict__ pnts,
                                               const float* __restrict__ dyn,
                                               float*       __restrict__ out) {
    __shared__ __align__(16) float sm[YTILE * NCH];   // 32 KB
    __shared__ int list[YTILE];
    __shared__ int cnt;

    int blk = blockIdx.x;
    int b   = blk / (XSZ * NYT);
    int rem = blk - b * (XSZ * NYT);
    int x   = rem / NYT;
    int y0  = (rem - x * NYT) * YTILE;

    int tid  = threadIdx.x;
    int lane = tid & 31;
    int wid  = tid >> 5;

    if (tid == 0) cnt = 0;
    // zero the smem tile
    {
        float4* smv = (float4*)sm;
        #pragma unroll
        for (int i = tid; i < YTILE * NCH / 4; i += 256)
            smv[i] = make_float4(0.f, 0.f, 0.f, 0.f);
    }
    __syncthreads();

    // gather active pixels; restore zero-marker invariant for next graph replay
    if (tid < YTILE) {
        int cell = (b * XSZ + x) * YSZ + y0 + tid;
        int v = g_idx[cell];
        if (v > 0) {
            int slot = atomicAdd(&cnt, 1);
            list[slot] = (tid << 15) | (v - 1);   // p < 20000 < 2^15
            g_idx[cell] = 0;
        }
    }
    __syncthreads();

    // warp-per-TWO-active-pixels sampling (doubled MLP per warp)
    int nact = cnt;
    for (int k = 2 * wid; k < nact; k += 16) {
        int e0 = list[k];
        if (k + 1 < nact) {
            int e1 = list[k + 1];
            do_point(e0, b, x, y0, lane, pnts, dyn, sm);
            do_point(e1, b, x, y0, lane, pnts, dyn, sm);
        } else {
            do_point(e0, b, x, y0, lane, pnts, dyn, sm);
        }
    }
    __syncthreads();

    // stream-out: warp = one channel, lane = y-quad; conflict-free LDS + STG.128.CS
    size_t base = ((size_t)b * NCH * XSZ + x) * YSZ + y0;
    #pragma unroll
    for (int i = tid; i < NCH * (YTILE / 4); i += 256) {
        int y4 = i & 31;          // lane == y4 -> coalesced 512B per warp
        int c  = i >> 5;
        int col = c ^ y4;         // (4*y4+j)>>2 == y4 for j in 0..3
        float4 v;
        v.x = sm[(4 * y4 + 0) * NCH + col];
        v.y = sm[(4 * y4 + 1) * NCH + col];
        v.z = sm[(4 * y4 + 2) * NCH + col];
        v.w = sm[(4 * y4 + 3) * NCH + col];
        __stcs((float4*)(out + base + (size_t)c * (XSZ * YSZ) + 4 * y4), v);
    }
}

// -------- launch --------
extern "C" void kernel_launch(void* const* d_in, const int* in_sizes, int n_in,
                              void* d_out, int out_size) {
    const float* c3      = (const float*)d_in[0];
    const float* c4      = (const float*)d_in[1];
    const float* c5      = (const float*)d_in[2];
    const float* dyn     = (const float*)d_in[3];
    const float* pnts    = (const float*)d_in[4];
    const int*   coors   = (const int*)  d_in[5];
    const int*   contain = (const int*)  d_in[6];
    float*       out     = (float*)d_out;

    // 1) combined scatter + transposes (independent work, one launch)
    k_pre<<<PRE_BLKS, dim3(32, 8)>>>(c3, c4, c5, coors, contain);
    // 2) fused zero + sample + blend + streaming output
    k_fused<<<BATCH * XSZ * NYT, 256>>>(pnts, dyn, out);
}

// round 15
// speedup vs baseline: 1.2774x; 1.2774x over previous
#include <cuda_runtime.h>

#define BATCH 4
#define NCH   64
#define NPTS  20000
#define XSZ   512
#define YSZ   512
#define YTILE 128
#define NYT   (YSZ / YTILE)   // 4

// feature-map pixel counts
#define P3 (48 * 160)   // 7680
#define P4 (24 * 80)    // 1920
#define P5 (12 * 40)    // 480

// -------- device scratch (zero-initialized; zero == empty marker) --------
__device__ int   g_idx[BATCH * XSZ * YSZ];      // winner (point index + 1) per pixel, 0 = empty
__device__ float g_t3[BATCH * P3 * NCH];        // features transposed to [b][pix][c]
__device__ float g_t4[BATCH * P4 * NCH];
__device__ float g_t5[BATCH * P5 * NCH];

// -------- combined prologue: transpose blocks + scatter blocks in one launch --------
#define T3_BLKS (BATCH * 2 * (P3 / 32))   // 1920
#define T4_BLKS (BATCH * 2 * (P4 / 32))   // 480
#define T5_BLKS (BATCH * 2 * (P5 / 32))   // 120
#define T_BLKS  (T3_BLKS + T4_BLKS + T5_BLKS)
#define SC_BLKS ((BATCH * NPTS + 255) / 256)   // 313
#define PRE_BLKS (T_BLKS + SC_BLKS)

__global__ void k_pre(const float* __restrict__ c3,
                      const float* __restrict__ c4,
                      const float* __restrict__ c5,
                      const int*   __restrict__ coors,
                      const int*   __restrict__ contain) {
    __shared__ float s[32][33];
    int bid = blockIdx.x;

    if (bid >= T_BLKS) {
        // ---- scatter: last-update-wins == highest (p+1) wins; 0 = empty ----
        int i = (bid - T_BLKS) * 256 + threadIdx.y * 32 + threadIdx.x;
        if (i >= BATCH * NPTS) return;
        if (contain[i] <= 0) return;
        int b  = i / NPTS;
        int p  = i - b * NPTS;
        int cx = coors[i * 3 + 1];
        int cy = coors[i * 3 + 2];
        if ((unsigned)cx >= XSZ || (unsigned)cy >= YSZ) return;
        atomicMax(&g_idx[(b * XSZ + cx) * YSZ + cy], p + 1);
        return;
    }

    // ---- tiled transpose: [C=64][P] -> [P][C=64] per (map, b) ----
    const float* src;
    float* dst;
    int P;
    if (bid < T3_BLKS)                { src = c3; dst = g_t3; P = P3; }
    else if (bid < T3_BLKS + T4_BLKS) { bid -= T3_BLKS; src = c4; dst = g_t4; P = P4; }
    else                              { bid -= T3_BLKS + T4_BLKS; src = c5; dst = g_t5; P = P5; }

    int ptiles = P >> 5;
    int b   = bid / (2 * ptiles);
    int rem = bid - b * (2 * ptiles);
    int c0  = (rem / ptiles) << 5;
    int p0  = (rem % ptiles) << 5;
    src += (size_t)b * NCH * P;
    dst += (size_t)b * P * NCH;

    int tx = threadIdx.x, ty = threadIdx.y;
    #pragma unroll
    for (int j = 0; j < 4; j++)
        s[ty + j * 8][tx] = src[(c0 + ty + j * 8) * P + p0 + tx];
    __syncthreads();
    #pragma unroll
    for (int j = 0; j < 4; j++)
        dst[(size_t)(p0 + ty + j * 8) * NCH + c0 + tx] = s[tx][ty + j * 8];
}

// -------- bilinear sample of one transposed map, warp-wide over channels --------
template<int H, int W>
__device__ __forceinline__ void sample_map(const float* __restrict__ t,   // [pix][C] for this batch
                                           float px, float py, int lane,
                                           float d, float2& acc) {
    float x = px * (float)(W - 1);
    float y = py * (float)(H - 1);
    float x0f = floorf(x), y0f = floorf(y);
    float wx = x - x0f,    wy = y - y0f;
    int x0 = (int)x0f, y0 = (int)y0f;
    int x1 = x0 + 1,   y1 = y0 + 1;

    float v00 = (x0 >= 0 && x0 < W && y0 >= 0 && y0 < H) ? 1.f : 0.f;
    float v10 = (x1 >= 0 && x1 < W && y0 >= 0 && y0 < H) ? 1.f : 0.f;
    float v01 = (x0 >= 0 && x0 < W && y1 >= 0 && y1 < H) ? 1.f : 0.f;
    float v11 = (x1 >= 0 && x1 < W && y1 >= 0 && y1 < H) ? 1.f : 0.f;

    int cx0 = min(max(x0, 0), W - 1);
    int cx1 = min(max(x1, 0), W - 1);
    int cy0 = min(max(y0, 0), H - 1);
    int cy1 = min(max(y1, 0), H - 1);

    float w00 = (1.f - wx) * (1.f - wy) * v00;
    float w10 =        wx  * (1.f - wy) * v10;
    float w01 = (1.f - wx) *        wy  * v01;
    float w11 =        wx  *        wy  * v11;

    const float2* p00 = (const float2*)(t + (cy0 * W + cx0) * NCH) + lane;
    const float2* p10 = (const float2*)(t + (cy0 * W + cx1) * NCH) + lane;
    const float2* p01 = (const float2*)(t + (cy1 * W + cx0) * NCH) + lane;
    const float2* p11 = (const float2*)(t + (cy1 * W + cx1) * NCH) + lane;
    float2 a00 = *p00, a10 = *p10, a01 = *p01, a11 = *p11;

    acc.x += d * (w00 * a00.x + w10 * a10.x + w01 * a01.x + w11 * a11.x);
    acc.y += d * (w00 * a00.y + w10 * a10.y + w01 * a01.y + w11 * a11.y);
}

// -------- fused: zero-fill + sample + blend, streaming the output once --------
// One block per (b, x, ytile=128). 256 threads = 8 warps; 6 blocks/SM.
// smem: flat 128x64, bank-swizzled: phys(y, c) = y*64 + (c ^ ((y>>2) & 31)).
// __launch_bounds__(256, 6) pins regs <= 42 (measured 40) to protect the
// 6-blocks/SM operating point — every deviation from it measured ~20us slower.
__global__ __launch_bounds__(256, 6) void k_fused(const float* __restrict__ pnts,
                                                  const float* __restrict__ dyn,
                                                  float*       __restrict__ out) {
    __shared__ __align__(16) float sm[YTILE * NCH];   // 32 KB
    __shared__ int list[YTILE];
    __shared__ int cnt;

    int blk = blockIdx.x;
    int b   = blk / (XSZ * NYT);
    int rem = blk - b * (XSZ * NYT);
    int x   = rem / NYT;
    int y0  = (rem - x * NYT) * YTILE;

    int tid  = threadIdx.x;
    int lane = tid & 31;
    int wid  = tid >> 5;

    if (tid == 0) cnt = 0;
    // zero the smem tile: 8 x STS.128 per thread
    {
        float4* smv = (float4*)sm;
        #pragma unroll
        for (int i = tid; i < YTILE * NCH / 4; i += 256)
            smv[i] = make_float4(0.f, 0.f, 0.f, 0.f);
    }
    __syncthreads();

    // gather active pixels; restore zero-marker invariant for next graph replay
    if (tid < YTILE) {
        int cell = (b * XSZ + x) * YSZ + y0 + tid;
        int v = g_idx[cell];
        if (v > 0) {
            int slot = atomicAdd(&cnt, 1);
            list[slot] = (tid << 15) | (v - 1);   // p < 20000 < 2^15
            g_idx[cell] = 0;
        }
    }
    __syncthreads();

    // warp-per-active-pixel sampling
    int nact = cnt;
    for (int k = wid; k < nact; k += 8) {
        int e    = list[k];
        int yloc = e >> 15;
        int p    = e & 0x7FFF;
        int cy   = y0 + yloc;

        float2 pxy = ((const float2*)pnts)[b * NPTS + p];
        float d0 = dyn[((b * 3 + 0) * XSZ + x) * YSZ + cy];
        float d1 = dyn[((b * 3 + 1) * XSZ + x) * YSZ + cy];
        float d2 = dyn[((b * 3 + 2) * XSZ + x) * YSZ + cy];

        float2 acc = make_float2(0.f, 0.f);
        sample_map<48, 160>(g_t3 + b * P3 * NCH, pxy.x, pxy.y, lane, d0, acc);
        sample_map<24,  80>(g_t4 + b * P4 * NCH, pxy.x, pxy.y, lane, d1, acc);
        sample_map<12,  40>(g_t5 + b * P5 * NCH, pxy.x, pxy.y, lane, d2, acc);

        int g = (yloc >> 2) & 31;
        sm[yloc * NCH + ((2 * lane)     ^ g)] = acc.x;
        sm[yloc * NCH + ((2 * lane + 1) ^ g)] = acc.y;
    }
    __syncthreads();

    // stream-out: warp = one channel, lane = y-quad; conflict-free LDS + STG.128.CS
    size_t base = ((size_t)b * NCH * XSZ + x) * YSZ + y0;
    #pragma unroll
    for (int i = tid; i < NCH * (YTILE / 4); i += 256) {
        int y4 = i & 31;          // lane == y4 -> coalesced 512B per warp
        int c  = i >> 5;
        int col = c ^ y4;         // (4*y4+j)>>2 == y4 for j in 0..3
        float4 v;
        v.x = sm[(4 * y4 + 0) * NCH + col];
        v.y = sm[(4 * y4 + 1) * NCH + col];
        v.z = sm[(4 * y4 + 2) * NCH + col];
        v.w = sm[(4 * y4 + 3) * NCH + col];
        __stcs((float4*)(out + base + (size_t)c * (XSZ * YSZ) + 4 * y4), v);
    }
}

// -------- launch --------
extern "C" void kernel_launch(void* const* d_in, const int* in_sizes, int n_in,
                              void* d_out, int out_size) {
    const float* c3      = (const float*)d_in[0];
    const float* c4      = (const float*)d_in[1];
    const float* c5      = (const float*)d_in[2];
    const float* dyn     = (const float*)d_in[3];
    const float* pnts    = (const float*)d_in[4];
    const int*   coors   = (const int*)  d_in[5];
    const int*   contain = (const int*)  d_in[6];
    float*       out     = (float*)d_out;

    // 1) combined scatter + transposes (independent work, one launch)
    k_pre<<<PRE_BLKS, dim3(32, 8)>>>(c3, c4, c5, coors, contain);
    // 2) fused zero + sample + blend + streaming output
    k_fused<<<BATCH * XSZ * NYT, 256>>>(pnts, dyn, out);
}